// round 16
// baseline (speedup 1.0000x reference)
#include <cuda_runtime.h>
#include <cstdint>
#include <math.h>

#define Hh 512
#define Wd 512
#define Cc 80
#define HW (Hh * Wd)
#define NBINS 4096
#define BINSHIFT 20
#define FLATBITS 25
#define FLATMASK ((1u << FLATBITS) - 1)
#define NCHUNK (Cc * (Hh / 8) * 4)   /* 20480 chunks: 8 rows x 128 cols */
#define HOT_CAP 4096
#define CAND_CAP 16384
#define SH_CAND 4096
#define NEGF (-__builtin_huge_valf())

// ---- scratch ----
__device__ unsigned int       g_hist[NBINS];     // self-cleaned by thresh
__device__ unsigned long long g_cm1[NCHUNK];     // per-chunk top-1 survivor composite
__device__ unsigned long long g_cm2[NCHUNK];     // per-chunk top-2 survivor composite
__device__ unsigned int       g_hot[HOT_CAP];    // chunks needing full rescan
__device__ unsigned int       g_nhot;
__device__ unsigned long long g_cand[CAND_CAP];
__device__ unsigned int       g_ncand;
__device__ unsigned int       g_thrkey;

__device__ __forceinline__ unsigned int fkey(float v) {
    unsigned int u = __float_as_uint(v);
    return (u & 0x80000000u) ? ~u : (u | 0x80000000u);
}
__device__ __forceinline__ float fkey_inv(unsigned int k) {
    unsigned int u = (k & 0x80000000u) ? (k ^ 0x80000000u) : ~k;
    return __uint_as_float(u);
}

// h from already-loaded v + halo scalars. SINGLE implementation shared by both
// passes -> bit-identical fmax sequence -> identical survivor predicates.
__device__ __forceinline__ void hv_from_v(const float4& v, float hl, float hr,
                                          int lane, float4& h) {
    float lft = __shfl_up_sync(0xffffffffu, v.w, 1);
    float rgt = __shfl_down_sync(0xffffffffu, v.x, 1);
    if (lane == 0)  lft = hl;
    if (lane == 31) rgt = hr;
    h.x = fmaxf(fmaxf(lft, v.x), v.y);
    h.y = fmaxf(fmaxf(v.x, v.y), v.z);
    h.z = fmaxf(fmaxf(v.y, v.z), v.w);
    h.w = fmaxf(fmaxf(v.z, v.w), rgt);
}

// Load the 10 rows of chunk (c, y0, g); all loads issued up-front (MLP=10).
__device__ __forceinline__ void load_chunk(const float* __restrict__ base,
                                           int y0, int g, int lane,
                                           float4* __restrict__ vr,
                                           float4* __restrict__ h) {
    float hl[10], hr[10];
    #pragma unroll
    for (int r = 0; r < 10; r++) {
        int yg = y0 - 1 + r;
        bool ok = (yg >= 0) && (yg < Hh);
        const float* row = base + (size_t)(ok ? yg : 0) * Wd;
        if (ok) {
            vr[r] = *(const float4*)(row + g * 128 + lane * 4);
            hl[r] = (lane == 0)  ? ((g > 0) ? row[g * 128 - 1]   : NEGF) : NEGF;
            hr[r] = (lane == 31) ? ((g < 3) ? row[g * 128 + 128] : NEGF) : NEGF;
        } else {
            vr[r].x = vr[r].y = vr[r].z = vr[r].w = NEGF;
            hl[r] = NEGF; hr[r] = NEGF;
        }
    }
    #pragma unroll
    for (int r = 0; r < 10; r++)
        hv_from_v(vr[r], hl[r], hr[r], lane, h[r]);
}

// ---- K1: per-warp chunk NMS + histogram + per-chunk TOP-2 survivor composites ----
__global__ __launch_bounds__(256) void nms_hist_kernel(const float* __restrict__ hmap) {
    __shared__ unsigned int shist[NBINS];       // 16 KB
    const int tid = threadIdx.x, lane = tid & 31, w = tid >> 5;
    for (int i = tid; i < NBINS; i += 256) shist[i] = 0u;
    __syncthreads();

    const unsigned int chunk = blockIdx.x * 8 + w;   // 20480 total
    const int g   = chunk & 3;
    const int ych = (chunk >> 2) & 63;
    const int c   = chunk >> 8;
    const int y0  = ych * 8;
    const float* __restrict__ base = hmap + (size_t)c * HW;

    float4 vr[10], h[10];
    load_chunk(base, y0, g, lane, vr, h);

    unsigned long long m1 = 0ull, m2 = 0ull;   // 0 = sentinel (no finite survivor maps to 0)
    #pragma unroll
    for (int r = 0; r < 8; r++) {
        float4 P = h[r], C = h[r + 1], N = h[r + 2], V = vr[r + 1];
        const unsigned int flrow = (unsigned int)c * HW + (unsigned int)(y0 + r) * Wd
                                 + (unsigned int)(g * 128 + lane * 4);
        float vv[4] = {V.x, V.y, V.z, V.w};
        float mm[4] = {fmaxf(fmaxf(P.x, C.x), N.x),
                       fmaxf(fmaxf(P.y, C.y), N.y),
                       fmaxf(fmaxf(P.z, C.z), N.z),
                       fmaxf(fmaxf(P.w, C.w), N.w)};
        #pragma unroll
        for (int e = 0; e < 4; e++) {
            if (mm[e] == vv[e]) {
                unsigned int key = fkey(vv[e]);
                atomicAdd(&shist[key >> BINSHIFT], 1u);
                unsigned long long comp = ((unsigned long long)key << FLATBITS)
                                        | (unsigned long long)(FLATMASK - (flrow + e));
                if (comp > m1) { m2 = m1; m1 = comp; }
                else if (comp > m2) { m2 = comp; }
            }
        }
    }

    // warp merge of top-2 pairs
    #pragma unroll
    for (int s = 16; s > 0; s >>= 1) {
        unsigned long long o1 = __shfl_xor_sync(0xffffffffu, m1, s);
        unsigned long long o2 = __shfl_xor_sync(0xffffffffu, m2, s);
        unsigned long long hi = m1 > o1 ? m1 : o1;
        unsigned long long lo = m1 > o1 ? o1 : m1;
        unsigned long long s2 = o2 > m2 ? o2 : m2;
        m1 = hi;
        m2 = lo > s2 ? lo : s2;
    }
    if (lane == 0) { g_cm1[chunk] = m1; g_cm2[chunk] = m2; }

    __syncthreads();
    for (int i = tid; i < NBINS; i += 256) {
        unsigned int s = shist[i];
        if (s) atomicAdd(&g_hist[i], s);
    }
}

// ---- K2: threshold over 4096 bins (1024 thr, 4 bins each; self-cleaning) ----
__global__ void thresh_kernel(int K) {
    __shared__ unsigned int s[1024];
    const int t = threadIdx.x;
    unsigned int hb[4];
    #pragma unroll
    for (int j = 0; j < 4; j++) {
        hb[j] = g_hist[t * 4 + j];
        g_hist[t * 4 + j] = 0u;           // clean for next graph replay
    }
    if (t == 0) { g_nhot = 0u; g_ncand = 0u; g_thrkey = 0u; }
    s[t] = hb[0] + hb[1] + hb[2] + hb[3];
    __syncthreads();
    for (int d = 1; d < 1024; d <<= 1) {
        unsigned int add = (t + d < 1024) ? s[t + d] : 0u;
        __syncthreads();
        s[t] += add;
        __syncthreads();
    }
    unsigned int cum = (t < 1023) ? s[t + 1] : 0u;   // count in bins >= 4(t+1)
    #pragma unroll
    for (int j = 3; j >= 0; j--) {
        unsigned int nc = cum + hb[j];
        if (nc >= (unsigned int)K && cum < (unsigned int)K)
            g_thrkey = (unsigned int)(t * 4 + j) << BINSHIFT;
        cum = nc;
    }
}

// ---- K2b: direct-append singleton chunks; queue multi-candidate chunks ----
__global__ void compact_kernel() {
    const unsigned int thr = g_thrkey;
    unsigned int i = blockIdx.x * blockDim.x + threadIdx.x;
    if (i >= NCHUNK) return;
    unsigned long long e1 = g_cm1[i];
    if ((unsigned int)(e1 >> FLATBITS) >= thr) {
        unsigned long long e2 = g_cm2[i];
        if ((unsigned int)(e2 >> FLATBITS) >= thr) {
            unsigned int p = atomicAdd(&g_nhot, 1u);   // rare: needs full rescan
            if (p < HOT_CAP) g_hot[p] = i;
        } else {
            unsigned int p = atomicAdd(&g_ncand, 1u);  // common: top-1 is the only one
            if (p < CAND_CAP) g_cand[p] = e1;
        }
    }
}

// ---- K3: full rescan of the few multi-candidate chunks ----
__global__ __launch_bounds__(128) void cand_kernel(const float* __restrict__ hmap) {
    const unsigned int nhot = min(g_nhot, (unsigned int)HOT_CAP);
    const unsigned int thr = g_thrkey;
    const int lane = threadIdx.x & 31;
    const unsigned int warps = gridDim.x * (blockDim.x >> 5);
    for (unsigned int wi = blockIdx.x * (blockDim.x >> 5) + (threadIdx.x >> 5);
         wi < nhot; wi += warps) {
        const unsigned int chunk = g_hot[wi];
        const int g   = chunk & 3;
        const int ych = (chunk >> 2) & 63;
        const int c   = chunk >> 8;
        const int y0  = ych * 8;
        const float* __restrict__ base = hmap + (size_t)c * HW;

        float4 vr[10], h[10];
        load_chunk(base, y0, g, lane, vr, h);

        #pragma unroll
        for (int r = 0; r < 8; r++) {
            float4 P = h[r], C = h[r + 1], N = h[r + 2], V = vr[r + 1];
            float vv[4] = {V.x, V.y, V.z, V.w};
            float mm[4] = {fmaxf(fmaxf(P.x, C.x), N.x),
                           fmaxf(fmaxf(P.y, C.y), N.y),
                           fmaxf(fmaxf(P.z, C.z), N.z),
                           fmaxf(fmaxf(P.w, C.w), N.w)};
            #pragma unroll
            for (int e = 0; e < 4; e++) {
                if (mm[e] == vv[e]) {
                    unsigned int key = fkey(vv[e]);
                    if (key >= thr) {
                        unsigned int fl = (unsigned int)c * HW
                                        + (unsigned int)(y0 + r) * Wd
                                        + (unsigned int)(g * 128 + lane * 4 + e);
                        unsigned int p = atomicAdd(&g_ncand, 1u);
                        if (p < CAND_CAP)
                            g_cand[p] = ((unsigned long long)key << FLATBITS)
                                      | (unsigned long long)(FLATMASK - fl);
                    }
                }
            }
        }
    }
}

// ---- K4: exact rank (multi-block); gather + write output ----
__global__ __launch_bounds__(256) void output_kernel(const float* __restrict__ regs,
                              const float* __restrict__ wh,
                              const float* __restrict__ rot,
                              float* __restrict__ out, int K) {
    __shared__ unsigned long long sk[SH_CAND];
    unsigned int n = min(g_ncand, (unsigned int)CAND_CAP);
    bool sh = (n <= (unsigned int)SH_CAND);
    if (sh)
        for (unsigned int i = threadIdx.x; i < n; i += blockDim.x)
            sk[i] = g_cand[i];
    __syncthreads();

    for (unsigned int i = blockIdx.x * blockDim.x + threadIdx.x; i < n;
         i += gridDim.x * blockDim.x) {
        unsigned long long ki = sh ? sk[i] : g_cand[i];
        int rank = 0;
        for (unsigned int j = 0; j < n; j++) {
            unsigned long long kj = sh ? sk[j] : g_cand[j];
            rank += (kj > ki) ? 1 : 0;
        }
        if (rank < K) {
            unsigned int key  = (unsigned int)(ki >> FLATBITS);
            unsigned int flat = FLATMASK - (unsigned int)(ki & FLATMASK);
            unsigned int c    = flat / HW;
            unsigned int idx  = flat - c * HW;
            float yf = (float)(idx >> 9);
            float xf = (float)(idx & 511u);
            float vv = fkey_inv(key);
            float score = 1.0f / (1.0f + expf(-vv));
            float* o = out + (size_t)rank * 7;
            o[0] = xf + __ldg(&regs[idx]);
            o[1] = yf + __ldg(&regs[HW + idx]);
            o[2] = __ldg(&wh[idx]);
            o[3] = __ldg(&wh[HW + idx]);
            o[4] = __ldg(&rot[idx]);
            o[5] = score;
            o[6] = (float)c;
        }
    }
}

extern "C" void kernel_launch(void* const* d_in, const int* in_sizes, int n_in,
                              void* d_out, int out_size) {
    const float* hmap = (const float*)d_in[0];
    const float* regs = (const float*)d_in[1];
    const float* wh   = (const float*)d_in[2];
    const float* rot  = (const float*)d_in[3];
    float* out = (float*)d_out;
    int K = out_size / 7;  // B=1; [B,K,7]

    nms_hist_kernel<<<NCHUNK / 8, 256>>>(hmap);   // 2560 blocks
    thresh_kernel<<<1, 1024>>>(K);
    compact_kernel<<<NCHUNK / 256, 256>>>();
    cand_kernel<<<64, 128>>>(hmap);
    output_kernel<<<32, 256>>>(regs, wh, rot, out, K);
}